// round 16
// baseline (speedup 1.0000x reference)
#include <cuda_runtime.h>
#include <math.h>

// ---------------------------------------------------------------------------
// Binarized network, fully fused. v15 = v14 +
//  split bit-accumulation chains: every serial "acc = 2*acc + bit" chain
//  (conv0: 32-long, conv blocks: 32-long x4, fc1/fc2: 16-long) is split into
//  two independent half-chains merged once with hi*65536+lo (IMAD, fma pipe).
//  Halves the dependent critical path that pinned issue at 68%.
// ---------------------------------------------------------------------------

struct __align__(16) CP {            // warp-uniform -> __constant__
    float c0[32][8];                 // s0..s3, conv_b, bn_m, bn_scale, bn_b
    uint4 wt[4][32];                 // {w0, w1, w2, ~thr}  (thr doubled for i=0)
};
struct __align__(16) SF {            // lane-divergent -> shared
    unsigned W1[1296];               // section q*324 + oo*20 + l (fc1 out q*16+oo)
    int      P5[68];                 // ~P5  (q*17 + oo)
    uint2    W2[68];                 // q*17 + oo {bits vs h0..31, h32..63}
    int      P6[68];                 // ~P6
    unsigned W3[2];
    float    sig[66];
};

__device__ CP g_cp;
__device__ SF g_sf;
__constant__ CP c_cp;

// (a^b)&c as a single LOP3 (immLut 0x28)
__device__ __forceinline__ unsigned xand(unsigned a, unsigned b, unsigned c) {
    unsigned r;
    asm("lop3.b32 %0, %1, %2, %3, 0x28;" : "=r"(r) : "r"(a), "r"(b), "r"(c));
    return r;
}
// a^b^c (immLut 0x96)
__device__ __forceinline__ unsigned xor3(unsigned a, unsigned b, unsigned c) {
    unsigned r;
    asm("lop3.b32 %0, %1, %2, %3, 0x96;" : "=r"(r) : "r"(a), "r"(b), "r"(c));
    return r;
}
// majority(a,b,c) (immLut 0xE8)
__device__ __forceinline__ unsigned maj3(unsigned a, unsigned b, unsigned c) {
    unsigned r;
    asm("lop3.b32 %0, %1, %2, %3, 0xE8;" : "=r"(r) : "r"(a), "r"(b), "r"(c));
    return r;
}
__device__ __forceinline__ void fadd(unsigned a, unsigned b, unsigned c,
                                     unsigned& s, unsigned& cy) {
    s = xor3(a, b, c);
    cy = maj3(a, b, c);
}

__device__ __forceinline__ float bnval(float z, float cb, float m, float sc, float bb) {
    float t1 = z + cb;
    float t2 = t1 - m;
    return fmaf(t2, sc, bb);
}

// first even z in [zmin, zmax] with bnval >= 0 (monotone); zmax+2 if none
__device__ int first_nonneg_z(int zmin, int zmax, float cb, float m, float sc, float bb) {
    int lo = zmin >> 1, hi = zmax >> 1;
    int ans = hi + 1;
    while (lo <= hi) {
        int mid = lo + ((hi - lo) >> 1);
        if (bnval((float)(2 * mid), cb, m, sc, bb) >= 0.f) { ans = mid; hi = mid - 1; }
        else lo = mid + 1;
    }
    return 2 * ans;
}

// Parallel prep: grid 128 x 128 threads = 512 warps; one warp per table entry.
__global__ void prep_kernel(
    const float* conv0_w, const float* conv0_b,
    const float* bn0_g, const float* bn0_b, const float* bn0_m, const float* bn0_v,
    const float* convs_w, const float* convs_b,
    const float* bns_g, const float* bns_b, const float* bns_m, const float* bns_v,
    const float* fc1_w, const float* fc1_b,
    const float* bn5_g, const float* bn5_b, const float* bn5_m, const float* bn5_v,
    const float* fc2_w, const float* fc2_b,
    const float* bn6_g, const float* bn6_b, const float* bn6_m, const float* bn6_v,
    const float* fc3_w, const float* fc3_b)
{
    const int lane = threadIdx.x & 31;
    const int W = blockIdx.x * (blockDim.x >> 5) + (threadIdx.x >> 5);
    const unsigned FULL = 0xffffffffu;

    if (W < 128) {
        int i = W >> 5, o = W & 31;
        unsigned wb0 = __ballot_sync(FULL, convs_w[((i * 32 + o) * 32 + lane) * 3 + 0] >= 0.f);
        unsigned wb1 = __ballot_sync(FULL, convs_w[((i * 32 + o) * 32 + lane) * 3 + 1] >= 0.f);
        unsigned wb2 = __ballot_sync(FULL, convs_w[((i * 32 + o) * 32 + lane) * 3 + 2] >= 0.f);
        if (lane == 0) {
            int oi = i * 32 + o;
            float cb = convs_b[oi], m = bns_m[oi], bb = bns_b[oi];
            float sc = __fdiv_rn(bns_g[oi], __fsqrt_rn(bns_v[oi] + 0.01f));
            int Ci = (i == 0) ? 96 : 192;
            int zth = first_nonneg_z(-(Ci + 2), Ci + 2, cb, m, sc, bb);
            int pmi = (Ci - zth) / 2;
            int thr = (i == 0) ? 2 * pmi : pmi;
            g_cp.wt[i][o] = make_uint4(wb0, wb1, wb2, (unsigned)(~thr));
        }
    } else if (W < 384) {
        int base = (W - 128) * 4;
#pragma unroll
        for (int t = 0; t < 4; t++) {
            int idx = base + t;
            int o = idx >> 4, l = idx & 15;
            unsigned w = __ballot_sync(FULL, fc1_w[o * 512 + lane * 16 + l] >= 0.f);
            if (lane == 0) g_sf.W1[(o >> 4) * 324 + (o & 15) * 20 + l] = w;
        }
    } else if (W < 448) {
        int o = W - 384;
        int rb = (o >> 4) * 324 + (o & 15) * 20;
        if (lane >= 1 && lane <= 4) g_sf.W1[rb + 15 + lane] = 0;
        if (lane == 0) {
            float cb = fc1_b[o], m = bn5_m[o], bb = bn5_b[o];
            float sc = __fdiv_rn(bn5_g[o], __fsqrt_rn(bn5_v[o] + 0.01f));
            int zth = first_nonneg_z(-1026, 1026, cb, m, sc, bb);
            g_sf.P5[(o >> 4) * 17 + (o & 15)] = ~((1024 - zth) / 2);
        }
    } else if (W < 480) {
        int o0 = (W - 448) * 2;
#pragma unroll
        for (int t = 0; t < 2; t++) {
            int o = o0 + t;
            unsigned w0 = __ballot_sync(FULL, fc2_w[o * 64 + lane] >= 0.f);
            unsigned w1 = __ballot_sync(FULL, fc2_w[o * 64 + 32 + lane] >= 0.f);
            if (lane == 0) {
                g_sf.W2[(o >> 4) * 17 + (o & 15)] = make_uint2(w0, w1);
                float cb = fc2_b[o], m = bn6_m[o], bb = bn6_b[o];
                float sc = __fdiv_rn(bn6_g[o], __fsqrt_rn(bn6_v[o] + 0.01f));
                int zth = first_nonneg_z(-66, 66, cb, m, sc, bb);
                g_sf.P6[(o >> 4) * 17 + (o & 15)] = ~((64 - zth) / 2);
            }
        }
    } else if (W == 480) {
        int o = lane;
        for (int c = 0; c < 4; c++)
            g_cp.c0[o][c] = (conv0_w[o * 4 + c] >= 0.f) ? 1.f : -1.f;
        float sc = __fdiv_rn(bn0_g[o], __fsqrt_rn(bn0_v[o] + 0.01f));
        g_cp.c0[o][4] = conv0_b[o];
        g_cp.c0[o][5] = bn0_m[o];
        g_cp.c0[o][6] = sc;
        g_cp.c0[o][7] = bn0_b[o];
    } else if (W == 481) {
        unsigned w0 = __ballot_sync(FULL, fc3_w[lane] >= 0.f);
        unsigned w1 = __ballot_sync(FULL, fc3_w[32 + lane] >= 0.f);
        if (lane == 0) { g_sf.W3[0] = w0; g_sf.W3[1] = w1; }
    } else if (W >= 482 && W < 485) {
        int p = (W - 482) * 32 + lane;
        if (p < 65) {
            float d = (float)(64 - 2 * p) + fc3_b[0];
            g_sf.sig[p] = 1.f / (1.f + expf(-d));
        }
    }
}

#define NT 128

__global__ __launch_bounds__(NT, 8) void bnn_kernel(
    const float* __restrict__ x, float* __restrict__ out, int B)
{
    __shared__ SF sf;
    __shared__ unsigned buf[32][36];   // [group][16 v0 | 16 mb | 4 pad]
    {
        const int n = (int)(sizeof(SF) / 4);
        const unsigned* src = (const unsigned*)&g_sf;
        unsigned* dst = (unsigned*)&sf;
        for (int i = threadIdx.x; i < n; i += NT) dst[i] = src[i];
    }
    __syncthreads();

    int gt = blockIdx.x * NT + threadIdx.x;
    int e = gt >> 2;
    int q = gt & 3;                   // position quarter: positions 4q..4q+3
    if (e >= B) return;
    const int grp = threadIdx.x >> 2;
    const unsigned FULL = 0xffffffffu;
    const bool edgeL = (q == 0);
    const bool edgeR = (q == 3);

    // ---- conv0 + bn0 + sign -> v0[1..4] (split 16+16 accumulator chains) ----
    unsigned v0[6];
    {
        const float* xb = x + (size_t)e * 64 + q * 4;
        float4 c0v = *(const float4*)(xb + 0);
        float4 c1v = *(const float4*)(xb + 16);
        float4 c2v = *(const float4*)(xb + 32);
        float4 c3v = *(const float4*)(xb + 48);
        float a0[4] = {c0v.x, c0v.y, c0v.z, c0v.w};
        float a1[4] = {c1v.x, c1v.y, c1v.z, c1v.w};
        float a2[4] = {c2v.x, c2v.y, c2v.z, c2v.w};
        float a3[4] = {c3v.x, c3v.y, c3v.z, c3v.w};
        unsigned accH[4] = {0u, 0u, 0u, 0u};
        unsigned accL[4] = {0u, 0u, 0u, 0u};
#pragma unroll 4
        for (int o = 31; o >= 0; o--) {
            float4 pA = *(const float4*)&c_cp.c0[o][0];
            float4 pB = *(const float4*)&c_cp.c0[o][4];
#pragma unroll
            for (int j = 0; j < 4; j++) {
                float y = pA.x * a0[j];
                y = fmaf(pA.y, a1[j], y);
                y = fmaf(pA.z, a2[j], y);
                y = fmaf(pA.w, a3[j], y);
                float t1 = y + pB.x;
                float t2 = t1 - pB.y;
                float v = fmaf(t2, pB.z, pB.w);
                unsigned bit = __float_as_uint(v) >> 31;   // v<0
                if (o >= 16) accH[j] = accH[j] + accH[j] + bit;
                else         accL[j] = accL[j] + accL[j] + bit;
            }
        }
#pragma unroll
        for (int j = 0; j < 4; j++)
            v0[j + 1] = ~(accH[j] * 65536u + accL[j]);   // bit set iff v>=0
    }
    // v0 halo (phantom content masked out by mb=0 later)
    {
        unsigned up = __shfl_up_sync(FULL, v0[4], 1);
        unsigned dn = __shfl_down_sync(FULL, v0[1], 1);
        v0[0] = up;
        v0[5] = dn;
    }

    // ---- 4 conv blocks, ONE unified two-plane path ---------------------------
    unsigned vc[6];
#pragma unroll
    for (int k = 0; k < 6; k++) vc[k] = v0[k];

#pragma unroll 1
    for (int i = 0; i < 4; i++) {
        {
            unsigned up = __shfl_up_sync(FULL, vc[4], 1);
            unsigned dn = __shfl_down_sync(FULL, vc[1], 1);
            vc[0] = up;
            vc[5] = dn;
        }
        unsigned mb[6];
        int DIm[4];
        {
            int pm[6];
#pragma unroll
            for (int k = 0; k < 6; k++) mb[k] = ~(v0[k] ^ vc[k]);
            mb[0] = edgeL ? 0u : mb[0];   // phantom: 0 taps, +32 into DI
            mb[5] = edgeR ? 0u : mb[5];
#pragma unroll
            for (int k = 0; k < 6; k++) pm[k] = __popc(mb[k]);
#pragma unroll
            for (int j = 0; j < 4; j++) DIm[j] = 96 - (pm[j] + pm[j + 1] + pm[j + 2]);
        }
        unsigned unH[4], unL[4];
#pragma unroll
        for (int j = 0; j < 4; j++) { unH[j] = 0; unL[j] = 0; }
#pragma unroll 4
        for (int o = 31; o >= 16; o--) {
            uint4 wt = c_cp.wt[i][o];
            int nthr = (int)wt.w;
#pragma unroll
            for (int j = 0; j < 4; j++) {
                unsigned a = xand(v0[j],     wt.x, mb[j]);
                unsigned b = xand(v0[j + 1], wt.y, mb[j + 1]);
                unsigned c = xand(v0[j + 2], wt.z, mb[j + 2]);
                int Pc = __popc(xor3(a, b, c)) + 2 * __popc(maj3(a, b, c));
                int d = 2 * Pc + DIm[j] + nthr;
                unH[j] = unH[j] + unH[j] + (((unsigned)d) >> 31);
            }
        }
#pragma unroll 4
        for (int o = 15; o >= 0; o--) {
            uint4 wt = c_cp.wt[i][o];
            int nthr = (int)wt.w;
#pragma unroll
            for (int j = 0; j < 4; j++) {
                unsigned a = xand(v0[j],     wt.x, mb[j]);
                unsigned b = xand(v0[j + 1], wt.y, mb[j + 1]);
                unsigned c = xand(v0[j + 2], wt.z, mb[j + 2]);
                int Pc = __popc(xor3(a, b, c)) + 2 * __popc(maj3(a, b, c));
                int d = 2 * Pc + DIm[j] + nthr;
                unL[j] = unL[j] + unL[j] + (((unsigned)d) >> 31);
            }
        }
#pragma unroll
        for (int j = 0; j < 4; j++) vc[j + 1] = unH[j] * 65536u + unL[j];
    }

    // ---- plane handoff: own v0 quad + own mb quad -> smem, read all 16 ---------
    unsigned mOwn[4];
    int Dsum;
    {
        int pms = 0;
#pragma unroll
        for (int j = 0; j < 4; j++) {
            mOwn[j] = ~(v0[j + 1] ^ vc[j + 1]);
            pms += __popc(mOwn[j]);
        }
        pms += __shfl_xor_sync(FULL, pms, 1);
        pms += __shfl_xor_sync(FULL, pms, 2);
        Dsum = 512 - pms;
    }
    {
        uint4* d0 = (uint4*)&buf[grp][4 * q];
        *d0 = make_uint4(v0[1], v0[2], v0[3], v0[4]);
        uint4* d1 = (uint4*)&buf[grp][16 + 4 * q];
        *d1 = make_uint4(mOwn[0], mOwn[1], mOwn[2], mOwn[3]);
    }
    __syncwarp();

    unsigned f0[16], mbf[16];
    {
        const uint4* b4 = (const uint4*)&buf[grp][0];
#pragma unroll
        for (int c = 0; c < 4; c++) {
            uint4 A = b4[c];
            uint4 M = b4[4 + c];
            f0[4 * c + 0] = A.x; f0[4 * c + 1] = A.y;
            f0[4 * c + 2] = A.z; f0[4 * c + 3] = A.w;
            mbf[4 * c + 0] = M.x; mbf[4 * c + 1] = M.y;
            mbf[4 * c + 2] = M.z; mbf[4 * c + 3] = M.w;
        }
    }

    // ---- fc1: 16 outputs per lane, CSA tree, split 8+8 chains ------------------
    const unsigned* W1s = &sf.W1[q * 324];
    const int* P5s = &sf.P5[q * 17];   // holds ~P5
    unsigned hbH = 0, hbL = 0;
#pragma unroll 2
    for (int oo = 15; oo >= 0; oo--) {
        const uint4* wv = (const uint4*)&W1s[oo * 20];
        unsigned t[16];
#pragma unroll
        for (int c = 0; c < 4; c++) {
            uint4 W = wv[c];
            t[4 * c + 0] = xand(f0[4 * c + 0], W.x, mbf[4 * c + 0]);
            t[4 * c + 1] = xand(f0[4 * c + 1], W.y, mbf[4 * c + 1]);
            t[4 * c + 2] = xand(f0[4 * c + 2], W.z, mbf[4 * c + 2]);
            t[4 * c + 3] = xand(f0[4 * c + 3], W.w, mbf[4 * c + 3]);
        }
        unsigned s0, s1, s2, s3, s4, c0, c1, c2, c3, c4;
        fadd(t[0],  t[1],  t[2],  s0, c0);
        fadd(t[3],  t[4],  t[5],  s1, c1);
        fadd(t[6],  t[7],  t[8],  s2, c2);
        fadd(t[9],  t[10], t[11], s3, c3);
        fadd(t[12], t[13], t[14], s4, c4);
        unsigned u0, u1, cc0, cc1;
        fadd(s0, s1, s2,    u0, cc0);
        fadd(s3, s4, t[15], u1, cc1);
        unsigned e0, e1, d0, d1;
        fadd(c0, c1, c2,  e0, d0);
        fadd(c3, c4, cc0, e1, d1);
        int p1 = __popc(u0) + __popc(u1);
        int p2 = __popc(e0) + __popc(e1) + __popc(cc1);
        int p4 = __popc(d0) + __popc(d1);
        int Pc = p1 + 2 * p2 + 4 * p4;
        int dd = 2 * Pc + Dsum + P5s[oo];        // <0 iff 2Pc+Dsum <= P5
        unsigned bit = ((unsigned)dd) >> 31;
        if (oo >= 8) hbH = hbH + hbH + bit;
        else         hbL = hbL + hbL + bit;
    }
    unsigned hb = hbH * 256u + hbL;
    // assemble natural h words: hw0 = outputs 0..31, hw1 = 32..63
    unsigned t1 = __shfl_xor_sync(FULL, hb, 1);
    unsigned pw = (q & 1) ? (t1 | (hb << 16)) : (hb | (t1 << 16));
    unsigned t2 = __shfl_xor_sync(FULL, pw, 2);
    unsigned hw0 = (q < 2) ? pw : t2;
    unsigned hw1 = (q < 2) ? t2 : pw;

    // ---- fc2: 16 outputs per lane, split 8+8 chains ------------------------------
    const uint2* W2s = &sf.W2[q * 17];
    const int* P6s = &sf.P6[q * 17];   // holds ~P6
    unsigned gbH = 0, gbL = 0;
#pragma unroll 4
    for (int oo = 15; oo >= 0; oo--) {
        uint2 W = W2s[oo];
        int P = __popc(hw0 ^ W.x) + __popc(hw1 ^ W.y);
        int dd = P + P6s[oo];                    // <0 iff P <= P6
        unsigned bit = ((unsigned)dd) >> 31;
        if (oo >= 8) gbH = gbH + gbH + bit;
        else         gbL = gbL + gbL + bit;
    }
    unsigned gb = gbH * 256u + gbL;
    t1 = __shfl_xor_sync(FULL, gb, 1);
    pw = (q & 1) ? (t1 | (gb << 16)) : (gb | (t1 << 16));
    t2 = __shfl_xor_sync(FULL, pw, 2);
    unsigned gw0 = (q < 2) ? pw : t2;
    unsigned gw1 = (q < 2) ? t2 : pw;

    // ---- fc3 + sigmoid LUT ----------------------------------------------------------
    if (q == 0) {
        int p3 = __popc(gw0 ^ sf.W3[0]) + __popc(gw1 ^ sf.W3[1]);
        out[e] = sf.sig[p3];
    }
}

extern "C" void kernel_launch(void* const* d_in, const int* in_sizes, int n_in,
                              void* d_out, int out_size)
{
    const float* x       = (const float*)d_in[0];
    const float* conv0_w = (const float*)d_in[1];
    const float* conv0_b = (const float*)d_in[2];
    const float* bn0_g   = (const float*)d_in[3];
    const float* bn0_b   = (const float*)d_in[4];
    const float* bn0_m   = (const float*)d_in[5];
    const float* bn0_v   = (const float*)d_in[6];
    const float* convs_w = (const float*)d_in[7];
    const float* convs_b = (const float*)d_in[8];
    const float* bns_g   = (const float*)d_in[9];
    const float* bns_b   = (const float*)d_in[10];
    const float* bns_m   = (const float*)d_in[11];
    const float* bns_v   = (const float*)d_in[12];
    const float* fc1_w   = (const float*)d_in[13];
    const float* fc1_b   = (const float*)d_in[14];
    const float* bn5_g   = (const float*)d_in[15];
    const float* bn5_b   = (const float*)d_in[16];
    const float* bn5_m   = (const float*)d_in[17];
    const float* bn5_v   = (const float*)d_in[18];
    const float* fc2_w   = (const float*)d_in[19];
    const float* fc2_b   = (const float*)d_in[20];
    const float* bn6_g   = (const float*)d_in[21];
    const float* bn6_b   = (const float*)d_in[22];
    const float* bn6_m   = (const float*)d_in[23];
    const float* bn6_v   = (const float*)d_in[24];
    const float* fc3_w   = (const float*)d_in[25];
    const float* fc3_b   = (const float*)d_in[26];

    int B = in_sizes[0] / 64;   // (B, 4, 16)
    float* out = (float*)d_out;

    prep_kernel<<<128, 128>>>(conv0_w, conv0_b, bn0_g, bn0_b, bn0_m, bn0_v,
                              convs_w, convs_b, bns_g, bns_b, bns_m, bns_v,
                              fc1_w, fc1_b, bn5_g, bn5_b, bn5_m, bn5_v,
                              fc2_w, fc2_b, bn6_g, bn6_b, bn6_m, bn6_v,
                              fc3_w, fc3_b);

    void* srcp = nullptr;
    cudaGetSymbolAddress(&srcp, g_cp);
    cudaMemcpyToSymbolAsync(c_cp, srcp, sizeof(CP), 0, cudaMemcpyDeviceToDevice, 0);

    long long totalThreads = 4LL * B;
    int blocks = (int)((totalThreads + NT - 1) / NT);
    bnn_kernel<<<blocks, NT>>>(x, out, B);
}

// round 17
// speedup vs baseline: 1.0441x; 1.0441x over previous
#include <cuda_runtime.h>
#include <math.h>

// ---------------------------------------------------------------------------
// Binarized network, fully fused. v16 = v14 (best, 92.5us kernel) +
//  - deeper fc1 CSA tree: 7 -> 5 POPCs per output (weights 1/2/4/8), trading
//    2 quarter-rate POPCs for 4 LOP3s (popc pipe is the more-loaded one)
//  - IMAD-form accumulates (acc*2+bit, Pc*2+base) to shift alu work onto the
//    15%-idle fma pipe
//  v15 chain-splitting reverted (measured neutral-negative).
// ---------------------------------------------------------------------------

struct __align__(16) CP {            // warp-uniform -> __constant__
    float c0[32][8];                 // s0..s3, conv_b, bn_m, bn_scale, bn_b
    uint4 wt[4][32];                 // {w0, w1, w2, ~thr}  (thr doubled for i=0)
};
struct __align__(16) SF {            // lane-divergent -> shared
    unsigned W1[1296];               // section q*324 + oo*20 + l (fc1 out q*16+oo)
    int      P5[68];                 // ~P5  (q*17 + oo)
    uint2    W2[68];                 // q*17 + oo {bits vs h0..31, h32..63}
    int      P6[68];                 // ~P6
    unsigned W3[2];
    float    sig[66];
};

__device__ CP g_cp;
__device__ SF g_sf;
__constant__ CP c_cp;

// (a^b)&c as a single LOP3 (immLut 0x28)
__device__ __forceinline__ unsigned xand(unsigned a, unsigned b, unsigned c) {
    unsigned r;
    asm("lop3.b32 %0, %1, %2, %3, 0x28;" : "=r"(r) : "r"(a), "r"(b), "r"(c));
    return r;
}
// a^b^c (immLut 0x96)
__device__ __forceinline__ unsigned xor3(unsigned a, unsigned b, unsigned c) {
    unsigned r;
    asm("lop3.b32 %0, %1, %2, %3, 0x96;" : "=r"(r) : "r"(a), "r"(b), "r"(c));
    return r;
}
// majority(a,b,c) (immLut 0xE8)
__device__ __forceinline__ unsigned maj3(unsigned a, unsigned b, unsigned c) {
    unsigned r;
    asm("lop3.b32 %0, %1, %2, %3, 0xE8;" : "=r"(r) : "r"(a), "r"(b), "r"(c));
    return r;
}
__device__ __forceinline__ void fadd(unsigned a, unsigned b, unsigned c,
                                     unsigned& s, unsigned& cy) {
    s = xor3(a, b, c);
    cy = maj3(a, b, c);
}

__device__ __forceinline__ float bnval(float z, float cb, float m, float sc, float bb) {
    float t1 = z + cb;
    float t2 = t1 - m;
    return fmaf(t2, sc, bb);
}

// first even z in [zmin, zmax] with bnval >= 0 (monotone); zmax+2 if none
__device__ int first_nonneg_z(int zmin, int zmax, float cb, float m, float sc, float bb) {
    int lo = zmin >> 1, hi = zmax >> 1;
    int ans = hi + 1;
    while (lo <= hi) {
        int mid = lo + ((hi - lo) >> 1);
        if (bnval((float)(2 * mid), cb, m, sc, bb) >= 0.f) { ans = mid; hi = mid - 1; }
        else lo = mid + 1;
    }
    return 2 * ans;
}

// Parallel prep: grid 128 x 128 threads = 512 warps; one warp per table entry.
__global__ void prep_kernel(
    const float* conv0_w, const float* conv0_b,
    const float* bn0_g, const float* bn0_b, const float* bn0_m, const float* bn0_v,
    const float* convs_w, const float* convs_b,
    const float* bns_g, const float* bns_b, const float* bns_m, const float* bns_v,
    const float* fc1_w, const float* fc1_b,
    const float* bn5_g, const float* bn5_b, const float* bn5_m, const float* bn5_v,
    const float* fc2_w, const float* fc2_b,
    const float* bn6_g, const float* bn6_b, const float* bn6_m, const float* bn6_v,
    const float* fc3_w, const float* fc3_b)
{
    const int lane = threadIdx.x & 31;
    const int W = blockIdx.x * (blockDim.x >> 5) + (threadIdx.x >> 5);
    const unsigned FULL = 0xffffffffu;

    if (W < 128) {
        int i = W >> 5, o = W & 31;
        unsigned wb0 = __ballot_sync(FULL, convs_w[((i * 32 + o) * 32 + lane) * 3 + 0] >= 0.f);
        unsigned wb1 = __ballot_sync(FULL, convs_w[((i * 32 + o) * 32 + lane) * 3 + 1] >= 0.f);
        unsigned wb2 = __ballot_sync(FULL, convs_w[((i * 32 + o) * 32 + lane) * 3 + 2] >= 0.f);
        if (lane == 0) {
            int oi = i * 32 + o;
            float cb = convs_b[oi], m = bns_m[oi], bb = bns_b[oi];
            float sc = __fdiv_rn(bns_g[oi], __fsqrt_rn(bns_v[oi] + 0.01f));
            int Ci = (i == 0) ? 96 : 192;
            int zth = first_nonneg_z(-(Ci + 2), Ci + 2, cb, m, sc, bb);
            int pmi = (Ci - zth) / 2;
            int thr = (i == 0) ? 2 * pmi : pmi;
            g_cp.wt[i][o] = make_uint4(wb0, wb1, wb2, (unsigned)(~thr));
        }
    } else if (W < 384) {
        int base = (W - 128) * 4;
#pragma unroll
        for (int t = 0; t < 4; t++) {
            int idx = base + t;
            int o = idx >> 4, l = idx & 15;
            unsigned w = __ballot_sync(FULL, fc1_w[o * 512 + lane * 16 + l] >= 0.f);
            if (lane == 0) g_sf.W1[(o >> 4) * 324 + (o & 15) * 20 + l] = w;
        }
    } else if (W < 448) {
        int o = W - 384;
        int rb = (o >> 4) * 324 + (o & 15) * 20;
        if (lane >= 1 && lane <= 4) g_sf.W1[rb + 15 + lane] = 0;
        if (lane == 0) {
            float cb = fc1_b[o], m = bn5_m[o], bb = bn5_b[o];
            float sc = __fdiv_rn(bn5_g[o], __fsqrt_rn(bn5_v[o] + 0.01f));
            int zth = first_nonneg_z(-1026, 1026, cb, m, sc, bb);
            g_sf.P5[(o >> 4) * 17 + (o & 15)] = ~((1024 - zth) / 2);
        }
    } else if (W < 480) {
        int o0 = (W - 448) * 2;
#pragma unroll
        for (int t = 0; t < 2; t++) {
            int o = o0 + t;
            unsigned w0 = __ballot_sync(FULL, fc2_w[o * 64 + lane] >= 0.f);
            unsigned w1 = __ballot_sync(FULL, fc2_w[o * 64 + 32 + lane] >= 0.f);
            if (lane == 0) {
                g_sf.W2[(o >> 4) * 17 + (o & 15)] = make_uint2(w0, w1);
                float cb = fc2_b[o], m = bn6_m[o], bb = bn6_b[o];
                float sc = __fdiv_rn(bn6_g[o], __fsqrt_rn(bn6_v[o] + 0.01f));
                int zth = first_nonneg_z(-66, 66, cb, m, sc, bb);
                g_sf.P6[(o >> 4) * 17 + (o & 15)] = ~((64 - zth) / 2);
            }
        }
    } else if (W == 480) {
        int o = lane;
        for (int c = 0; c < 4; c++)
            g_cp.c0[o][c] = (conv0_w[o * 4 + c] >= 0.f) ? 1.f : -1.f;
        float sc = __fdiv_rn(bn0_g[o], __fsqrt_rn(bn0_v[o] + 0.01f));
        g_cp.c0[o][4] = conv0_b[o];
        g_cp.c0[o][5] = bn0_m[o];
        g_cp.c0[o][6] = sc;
        g_cp.c0[o][7] = bn0_b[o];
    } else if (W == 481) {
        unsigned w0 = __ballot_sync(FULL, fc3_w[lane] >= 0.f);
        unsigned w1 = __ballot_sync(FULL, fc3_w[32 + lane] >= 0.f);
        if (lane == 0) { g_sf.W3[0] = w0; g_sf.W3[1] = w1; }
    } else if (W >= 482 && W < 485) {
        int p = (W - 482) * 32 + lane;
        if (p < 65) {
            float d = (float)(64 - 2 * p) + fc3_b[0];
            g_sf.sig[p] = 1.f / (1.f + expf(-d));
        }
    }
}

#define NT 128

__global__ __launch_bounds__(NT, 8) void bnn_kernel(
    const float* __restrict__ x, float* __restrict__ out, int B)
{
    __shared__ SF sf;
    __shared__ unsigned buf[32][36];   // [group][16 v0 | 16 mb | 4 pad]
    {
        const int n = (int)(sizeof(SF) / 4);
        const unsigned* src = (const unsigned*)&g_sf;
        unsigned* dst = (unsigned*)&sf;
        for (int i = threadIdx.x; i < n; i += NT) dst[i] = src[i];
    }
    __syncthreads();

    int gt = blockIdx.x * NT + threadIdx.x;
    int e = gt >> 2;
    int q = gt & 3;                   // position quarter: positions 4q..4q+3
    if (e >= B) return;
    const int grp = threadIdx.x >> 2;
    const unsigned FULL = 0xffffffffu;
    const bool edgeL = (q == 0);
    const bool edgeR = (q == 3);

    // ---- conv0 + bn0 + sign -> v0[1..4] (sign-bit arithmetic, no FSETP) -----
    unsigned v0[6];
    {
        const float* xb = x + (size_t)e * 64 + q * 4;
        float4 c0v = *(const float4*)(xb + 0);
        float4 c1v = *(const float4*)(xb + 16);
        float4 c2v = *(const float4*)(xb + 32);
        float4 c3v = *(const float4*)(xb + 48);
        float a0[4] = {c0v.x, c0v.y, c0v.z, c0v.w};
        float a1[4] = {c1v.x, c1v.y, c1v.z, c1v.w};
        float a2[4] = {c2v.x, c2v.y, c2v.z, c2v.w};
        float a3[4] = {c3v.x, c3v.y, c3v.z, c3v.w};
        unsigned acc[4] = {0u, 0u, 0u, 0u};
#pragma unroll 4
        for (int o = 31; o >= 0; o--) {
            float4 pA = *(const float4*)&c_cp.c0[o][0];
            float4 pB = *(const float4*)&c_cp.c0[o][4];
#pragma unroll
            for (int j = 0; j < 4; j++) {
                float y = pA.x * a0[j];
                y = fmaf(pA.y, a1[j], y);
                y = fmaf(pA.z, a2[j], y);
                y = fmaf(pA.w, a3[j], y);
                float t1 = y + pB.x;
                float t2 = t1 - pB.y;
                float v = fmaf(t2, pB.z, pB.w);
                acc[j] = acc[j] * 2u + (__float_as_uint(v) >> 31);  // v<0 bit
            }
        }
#pragma unroll
        for (int j = 0; j < 4; j++) v0[j + 1] = ~acc[j];   // bit set iff v>=0
    }
    // v0 halo (phantom content masked out by mb=0 later)
    {
        unsigned up = __shfl_up_sync(FULL, v0[4], 1);
        unsigned dn = __shfl_down_sync(FULL, v0[1], 1);
        v0[0] = up;
        v0[5] = dn;
    }

    // ---- 4 conv blocks, ONE unified two-plane path ---------------------------
    unsigned vc[6];
#pragma unroll
    for (int k = 0; k < 6; k++) vc[k] = v0[k];

#pragma unroll 1
    for (int i = 0; i < 4; i++) {
        {
            unsigned up = __shfl_up_sync(FULL, vc[4], 1);
            unsigned dn = __shfl_down_sync(FULL, vc[1], 1);
            vc[0] = up;
            vc[5] = dn;
        }
        unsigned mb[6];
        int DIm[4];
        {
            int pm[6];
#pragma unroll
            for (int k = 0; k < 6; k++) mb[k] = ~(v0[k] ^ vc[k]);
            mb[0] = edgeL ? 0u : mb[0];   // phantom: 0 taps, +32 into DI
            mb[5] = edgeR ? 0u : mb[5];
#pragma unroll
            for (int k = 0; k < 6; k++) pm[k] = __popc(mb[k]);
#pragma unroll
            for (int j = 0; j < 4; j++) DIm[j] = 96 - (pm[j] + pm[j + 1] + pm[j + 2]);
        }
        unsigned un[4];
#pragma unroll
        for (int j = 0; j < 4; j++) un[j] = 0;
#pragma unroll 4
        for (int o = 31; o >= 0; o--) {
            uint4 wt = c_cp.wt[i][o];
            int nthr = (int)wt.w;         // ~thr
#pragma unroll
            for (int j = 0; j < 4; j++) {
                unsigned a = xand(v0[j],     wt.x, mb[j]);
                unsigned b = xand(v0[j + 1], wt.y, mb[j + 1]);
                unsigned c = xand(v0[j + 2], wt.z, mb[j + 2]);
                int Pc = __popc(xor3(a, b, c)) + 2 * __popc(maj3(a, b, c));
                int d = Pc * 2 + (DIm[j] + nthr);       // <0 iff value <= thr
                un[j] = un[j] * 2u + (((unsigned)d) >> 31);
            }
        }
#pragma unroll
        for (int j = 0; j < 4; j++) vc[j + 1] = un[j];
    }

    // ---- plane handoff: own v0 quad + own mb quad -> smem, read all 16 ---------
    unsigned mOwn[4];
    int Dsum;
    {
        int pms = 0;
#pragma unroll
        for (int j = 0; j < 4; j++) {
            mOwn[j] = ~(v0[j + 1] ^ vc[j + 1]);
            pms += __popc(mOwn[j]);
        }
        pms += __shfl_xor_sync(FULL, pms, 1);
        pms += __shfl_xor_sync(FULL, pms, 2);
        Dsum = 512 - pms;
    }
    {
        uint4* d0 = (uint4*)&buf[grp][4 * q];
        *d0 = make_uint4(v0[1], v0[2], v0[3], v0[4]);
        uint4* d1 = (uint4*)&buf[grp][16 + 4 * q];
        *d1 = make_uint4(mOwn[0], mOwn[1], mOwn[2], mOwn[3]);
    }
    __syncwarp();

    unsigned f0[16], mbf[16];
    {
        const uint4* b4 = (const uint4*)&buf[grp][0];
#pragma unroll
        for (int c = 0; c < 4; c++) {
            uint4 A = b4[c];
            uint4 M = b4[4 + c];
            f0[4 * c + 0] = A.x; f0[4 * c + 1] = A.y;
            f0[4 * c + 2] = A.z; f0[4 * c + 3] = A.w;
            mbf[4 * c + 0] = M.x; mbf[4 * c + 1] = M.y;
            mbf[4 * c + 2] = M.z; mbf[4 * c + 3] = M.w;
        }
    }

    // ---- fc1: 16 outputs per lane, deep CSA tree (5 POPC per output) -----------
    const unsigned* W1s = &sf.W1[q * 324];
    const int* P5s = &sf.P5[q * 17];   // holds ~P5
    unsigned hb = 0;
#pragma unroll 2
    for (int oo = 15; oo >= 0; oo--) {
        const uint4* wv = (const uint4*)&W1s[oo * 20];
        unsigned t[16];
#pragma unroll
        for (int c = 0; c < 4; c++) {
            uint4 W = wv[c];
            t[4 * c + 0] = xand(f0[4 * c + 0], W.x, mbf[4 * c + 0]);
            t[4 * c + 1] = xand(f0[4 * c + 1], W.y, mbf[4 * c + 1]);
            t[4 * c + 2] = xand(f0[4 * c + 2], W.z, mbf[4 * c + 2]);
            t[4 * c + 3] = xand(f0[4 * c + 3], W.w, mbf[4 * c + 3]);
        }
        // level 1: five 3:2 compressors over t0..t14 (t15 passes)
        unsigned s0, s1, s2, s3, s4, c0, c1, c2, c3, c4;
        fadd(t[0],  t[1],  t[2],  s0, c0);
        fadd(t[3],  t[4],  t[5],  s1, c1);
        fadd(t[6],  t[7],  t[8],  s2, c2);
        fadd(t[9],  t[10], t[11], s3, c3);
        fadd(t[12], t[13], t[14], s4, c4);
        // level 2 weight-1
        unsigned u0, u1, cc0, cc1;
        fadd(s0, s1, s2,    u0, cc0);
        fadd(s3, s4, t[15], u1, cc1);
        // level 2 weight-2
        unsigned e0, e1, d0, d1;
        fadd(c0, c1, c2,  e0, d0);
        fadd(c3, c4, cc0, e1, d1);
        // level 3: compress weight-2 {e0,e1,cc1} and weight-4 {d0,d1,d2}
        unsigned e2, d2, f4, g8;
        fadd(e0, e1, cc1, e2, d2);
        fadd(d0, d1, d2,  f4, g8);
        // final: u0,u1 (w1), e2 (w2), f4 (w4), g8 (w8)  -> 5 POPCs
        int Pc = __popc(u0) + __popc(u1)
               + __popc(e2) * 2 + __popc(f4) * 4 + __popc(g8) * 8;
        int dd = Pc * 2 + (Dsum + P5s[oo]);      // <0 iff 2Pc+Dsum <= P5
        hb = hb * 2u + (((unsigned)dd) >> 31);
    }
    // assemble natural h words: hw0 = outputs 0..31, hw1 = 32..63
    unsigned t1 = __shfl_xor_sync(FULL, hb, 1);
    unsigned pw = (q & 1) ? (t1 | (hb << 16)) : (hb | (t1 << 16));
    unsigned t2 = __shfl_xor_sync(FULL, pw, 2);
    unsigned hw0 = (q < 2) ? pw : t2;
    unsigned hw1 = (q < 2) ? t2 : pw;

    // ---- fc2: 16 outputs per lane -------------------------------------------------
    const uint2* W2s = &sf.W2[q * 17];
    const int* P6s = &sf.P6[q * 17];   // holds ~P6
    unsigned gb = 0;
#pragma unroll 4
    for (int oo = 15; oo >= 0; oo--) {
        uint2 W = W2s[oo];
        int P = __popc(hw0 ^ W.x) + __popc(hw1 ^ W.y);
        int dd = P + P6s[oo];                    // <0 iff P <= P6
        gb = gb * 2u + (((unsigned)dd) >> 31);
    }
    t1 = __shfl_xor_sync(FULL, gb, 1);
    pw = (q & 1) ? (t1 | (gb << 16)) : (gb | (t1 << 16));
    t2 = __shfl_xor_sync(FULL, pw, 2);
    unsigned gw0 = (q < 2) ? pw : t2;
    unsigned gw1 = (q < 2) ? t2 : pw;

    // ---- fc3 + sigmoid LUT ----------------------------------------------------------
    if (q == 0) {
        int p3 = __popc(gw0 ^ sf.W3[0]) + __popc(gw1 ^ sf.W3[1]);
        out[e] = sf.sig[p3];
    }
}

extern "C" void kernel_launch(void* const* d_in, const int* in_sizes, int n_in,
                              void* d_out, int out_size)
{
    const float* x       = (const float*)d_in[0];
    const float* conv0_w = (const float*)d_in[1];
    const float* conv0_b = (const float*)d_in[2];
    const float* bn0_g   = (const float*)d_in[3];
    const float* bn0_b   = (const float*)d_in[4];
    const float* bn0_m   = (const float*)d_in[5];
    const float* bn0_v   = (const float*)d_in[6];
    const float* convs_w = (const float*)d_in[7];
    const float* convs_b = (const float*)d_in[8];
    const float* bns_g   = (const float*)d_in[9];
    const float* bns_b   = (const float*)d_in[10];
    const float* bns_m   = (const float*)d_in[11];
    const float* bns_v   = (const float*)d_in[12];
    const float* fc1_w   = (const float*)d_in[13];
    const float* fc1_b   = (const float*)d_in[14];
    const float* bn5_g   = (const float*)d_in[15];
    const float* bn5_b   = (const float*)d_in[16];
    const float* bn5_m   = (const float*)d_in[17];
    const float* bn5_v   = (const float*)d_in[18];
    const float* fc2_w   = (const float*)d_in[19];
    const float* fc2_b   = (const float*)d_in[20];
    const float* bn6_g   = (const float*)d_in[21];
    const float* bn6_b   = (const float*)d_in[22];
    const float* bn6_m   = (const float*)d_in[23];
    const float* bn6_v   = (const float*)d_in[24];
    const float* fc3_w   = (const float*)d_in[25];
    const float* fc3_b   = (const float*)d_in[26];

    int B = in_sizes[0] / 64;   // (B, 4, 16)
    float* out = (float*)d_out;

    prep_kernel<<<128, 128>>>(conv0_w, conv0_b, bn0_g, bn0_b, bn0_m, bn0_v,
                              convs_w, convs_b, bns_g, bns_b, bns_m, bns_v,
                              fc1_w, fc1_b, bn5_g, bn5_b, bn5_m, bn5_v,
                              fc2_w, fc2_b, bn6_g, bn6_b, bn6_m, bn6_v,
                              fc3_w, fc3_b);

    void* srcp = nullptr;
    cudaGetSymbolAddress(&srcp, g_cp);
    cudaMemcpyToSymbolAsync(c_cp, srcp, sizeof(CP), 0, cudaMemcpyDeviceToDevice, 0);

    long long totalThreads = 4LL * B;
    int blocks = (int)((totalThreads + NT - 1) / NT);
    bnn_kernel<<<blocks, NT>>>(x, out, B);
}